// round 15
// baseline (speedup 1.0000x reference)
#include <cuda_runtime.h>
#include <math.h>

#define N_MAX   196608
#define TILE    96
#define TMAX    2048
#define MAXDET  100
#define MAXC    448           // candidate cap (matrix capacity)
#define WORDS   14            // MAXC / 32
#define SPAN    128u          // window below max, ordered-ulp units
#define LOU     0xBC23D70Au   // ordf(0.01f)
#define NMS_T   512

// decode tiling (C==90 fast path)
#define DT_PAIRS 32                     // pairs per tile
#define DT_BYTES (DT_PAIRS * 720)       // 23040 B (45 float4 per pair)
#define DT_TPB   2                      // tiles per block, ALL primed up-front

__device__ float              g_scores[N_MAX];
__device__ unsigned           g_maxu;     // zero-init; reset by nms each replay
__device__ int                g_count;    // reset by nms each replay
__device__ unsigned long long g_candKey[MAXC];
__device__ float4             g_candBox[MAXC];

__device__ __forceinline__ unsigned ordf(float f) {
    unsigned u = __float_as_uint(f);
    return (u & 0x80000000u) ? ~u : (u | 0x80000000u);
}
__device__ __forceinline__ float unordf(unsigned u) {
    return __uint_as_float((u & 0x80000000u) ? (u ^ 0x80000000u) : ~u);
}
__device__ __forceinline__ float read_dim(const void* p) {
    int iv = *(const int*)p;
    if (iv >= 1 && iv <= (1 << 20)) return (float)iv;
    float fv = *(const float*)p;
    if (fv >= 1.0f && fv <= 1048576.0f) return fv;
    double dv = *(const double*)p;
    if (dv >= 1.0 && dv <= 1048576.0) return (float)dv;
    long long lv = *(const long long*)p;
    return (float)lv;
}
// iou > 0.5  <=>  inter > 0.5*den  (den > 0 always; exact comparison, no div)
__device__ __forceinline__ bool iou_gt_half(float4 A, float4 B) {
    float x1 = fmaxf(A.x, B.x), y1 = fmaxf(A.y, B.y);
    float x2 = fminf(A.z, B.z), y2 = fminf(A.w, B.w);
    float inter = fmaxf(x2 - x1, 0.0f) * fmaxf(y2 - y1, 0.0f);
    float a1 = (A.z - A.x) * (A.w - A.y);
    float a2 = (B.z - B.x) * (B.w - B.y);
    float den = ((a1 + a2) - inter) + 1e-8f;   // match reference association
    return inter > 0.5f * den;
}
__device__ __forceinline__ float4 make_box(float4 a, float4 r,
                                           float imh, float imw) {
    float wa  = a.z - a.x;
    float ha  = a.w - a.y;
    float cxa = a.x + 0.5f * wa;
    float cya = a.y + 0.5f * ha;
    float cx  = cxa + r.x * 0.1f * wa;
    float cy  = cya + r.y * 0.1f * ha;
    float w   = expf(r.z * 0.2f) * wa;
    float h   = expf(r.w * 0.2f) * ha;
    float4 b;
    b.x = fminf(fmaxf(cx - 0.5f * w, 0.0f), imw);
    b.y = fminf(fmaxf(cy - 0.5f * h, 0.0f), imh);
    b.z = fminf(fmaxf(cx + 0.5f * w, 0.0f), imw);
    b.w = fminf(fmaxf(cy + 0.5f * h, 0.0f), imh);
    return b;
}
__device__ __forceinline__ unsigned ord4max(float4 v) {
    return ordf(fmaxf(fmaxf(v.x, v.y), fmaxf(v.z, v.w)));
}
__device__ __forceinline__ unsigned smem_u32(const void* p) {
    return (unsigned)__cvta_generic_to_shared(p);
}
__device__ __forceinline__ void mbar_init(unsigned mb, unsigned cnt) {
    asm volatile("mbarrier.init.shared.b64 [%0], %1;" :: "r"(mb), "r"(cnt) : "memory");
}
__device__ __forceinline__ void mbar_expect_tx(unsigned mb, unsigned bytes) {
    asm volatile("mbarrier.arrive.expect_tx.shared.b64 _, [%0], %1;"
                 :: "r"(mb), "r"(bytes) : "memory");
}
__device__ __forceinline__ void mbar_wait(unsigned mb, unsigned parity) {
    asm volatile(
        "{\n\t.reg .pred P;\n\t"
        "WAIT_%=:\n\t"
        "mbarrier.try_wait.parity.acquire.cta.shared::cta.b64 P, [%0], %1;\n\t"
        "@!P bra WAIT_%=;\n\t}"
        :: "r"(mb), "r"(parity) : "memory");
}
__device__ __forceinline__ void bulk_ld(unsigned sdst, const void* gsrc,
                                        unsigned bytes, unsigned mb) {
    asm volatile(
        "cp.async.bulk.shared::cta.global.mbarrier::complete_tx::bytes "
        "[%0], [%1], %2, [%3];"
        :: "r"(sdst), "l"(gsrc), "r"(bytes), "r"(mb) : "memory");
}

// ---------------------------------------------------------------------------
// Kernel 1 (C==90): bulk-async decode, both tiles primed at block start —
// no mid-kernel refill chain. Block churn (CLC) provides cross-block
// pipelining; 4 blocks/SM x 2 tiles = 184KB in flight per SM.
// ---------------------------------------------------------------------------
__global__ void __launch_bounds__(256)
decode90_kernel(const float* __restrict__ cls, int N) {
    __shared__ __align__(128) char sBuf[2][DT_BYTES];
    __shared__ __align__(8) unsigned long long sMbar[2];
    const unsigned FULL = 0xffffffffu;
    int tid = threadIdx.x;
    int sub = tid & 7;
    int grp = tid >> 3;                  // pair-within-tile [0,32)
    int pairs = N >> 1;
    int nTiles = (pairs + DT_PAIRS - 1) / DT_PAIRS;
    long long tile0 = (long long)blockIdx.x * DT_TPB;
    int nT = (int)min((long long)DT_TPB, (long long)nTiles - tile0);

    unsigned mb0 = smem_u32(&sMbar[0]);
    unsigned mb1 = smem_u32(&sMbar[1]);
    unsigned sb0 = smem_u32(&sBuf[0][0]);
    unsigned sb1 = smem_u32(&sBuf[1][0]);

    if (nT > 0) {
        if (tid == 0) {
            mbar_init(mb0, 1);
            mbar_init(mb1, 1);
        }
        __syncthreads();

        // prime ALL tiles for this block
        if (tid == 0) {
            #pragma unroll
            for (int k = 0; k < DT_TPB; k++) {
                if (k < nT) {
                    long long t = tile0 + k;
                    int pIn = (int)min((long long)DT_PAIRS,
                                       (long long)pairs - t * DT_PAIRS);
                    unsigned bytes = (unsigned)(pIn * 720);
                    unsigned mb = k ? mb1 : mb0;
                    unsigned sb = k ? sb1 : sb0;
                    mbar_expect_tx(mb, bytes);
                    bulk_ld(sb, (const char*)cls + t * (long long)DT_BYTES,
                            bytes, mb);
                }
            }
        }

        unsigned wm = 0u;
        #pragma unroll
        for (int k = 0; k < DT_TPB; k++) {
            if (k >= nT) break;
            mbar_wait(k ? mb1 : mb0, 0u);

            long long t = tile0 + k;
            int pIn = (int)min((long long)DT_PAIRS,
                               (long long)pairs - t * DT_PAIRS);

            unsigned mA = 0u, mB = 0u;
            if (grp < pIn) {
                const float4* rowp = (const float4*)&sBuf[k][0] + grp * 45;
                float4 va[6];
                #pragma unroll
                for (int it = 0; it < 6; it++) {
                    int q  = sub + it * 8;
                    int qc = (q < 45) ? q : 0;
                    va[it] = rowp[qc];
                }
                #pragma unroll
                for (int it = 0; it < 6; it++) {
                    int q = sub + it * 8;
                    if (q < 45) {
                        float4 x = va[it];
                        if (q < 22) {
                            mA = max(mA, ord4max(x));
                        } else if (q == 22) {   // floats 88..91: x,y->A; z,w->B
                            mA = max(mA, ordf(fmaxf(x.x, x.y)));
                            mB = max(mB, ordf(fmaxf(x.z, x.w)));
                        } else {
                            mB = max(mB, ord4max(x));
                        }
                    }
                }
            }
            #pragma unroll
            for (int off = 1; off <= 4; off <<= 1) {
                mA = max(mA, __shfl_xor_sync(FULL, mA, off));
                mB = max(mB, __shfl_xor_sync(FULL, mB, off));
            }
            if (grp < pIn && sub < 2) {
                unsigned u = sub ? mB : mA;
                float best = unordf(u);
                g_scores[2 * (t * DT_PAIRS + grp) + sub] =
                    (best > 0.01f) ? best : -INFINITY;
            }
            wm = max(wm, max(mA, mB));
        }

        // one global atomic per warp
        wm = max(wm, __shfl_xor_sync(FULL, wm, 8));
        wm = max(wm, __shfl_xor_sync(FULL, wm, 16));
        #pragma unroll
        for (int off = 1; off <= 4; off <<= 1)
            wm = max(wm, __shfl_xor_sync(FULL, wm, off));
        if ((tid & 31) == 0) atomicMax(&g_maxu, wm);
    }

    // odd-N tail anchor
    if ((N & 1) && blockIdx.x == 0 && tid == 0) {
        const float* row = cls + (long long)(N - 1) * 90;
        unsigned u = 0u;
        for (int j = 0; j < 90; j++) u = max(u, ordf(row[j]));
        float best = unordf(u);
        g_scores[N - 1] = (best > 0.01f) ? best : -INFINITY;
        atomicMax(&g_maxu, u);
    }
}

// Generic-C path: warp per anchor.
__global__ void decodegen_kernel(const float* __restrict__ cls, int N, int C) {
    const unsigned FULL = 0xffffffffu;
    int warp = (blockIdx.x * blockDim.x + threadIdx.x) >> 5;
    int lane = threadIdx.x & 31;
    if (warp >= N) return;
    const float* row = cls + (long long)warp * C;
    unsigned u = 0u;
    for (int j = lane; j < C; j += 32) u = max(u, ordf(row[j]));
    #pragma unroll
    for (int off = 16; off; off >>= 1)
        u = max(u, __shfl_xor_sync(FULL, u, off));
    if (lane == 0) {
        float best = unordf(u);
        g_scores[warp] = (best > 0.01f) ? best : -INFINITY;
        atomicMax(&g_maxu, u);
    }
}

// ---------------------------------------------------------------------------
// Kernel 2: grid-wide compact (float4-vectorized) + box decode. PDL.
// ---------------------------------------------------------------------------
__global__ void compact_kernel(const float* __restrict__ reg,
                               const float* __restrict__ anc,
                               const void* ph, const void* pw, int N) {
    cudaGridDependencySynchronize();

    int t = blockIdx.x * blockDim.x + threadIdx.x;
    unsigned maxu = g_maxu;
    unsigned cut = (maxu > LOU + 1u + SPAN) ? (maxu - SPAN) : (LOU + 1u);

    int n4 = N >> 2;
    if (t < n4) {
        float4 v = ((const float4*)g_scores)[t];
        float vv[4] = {v.x, v.y, v.z, v.w};
        #pragma unroll
        for (int c = 0; c < 4; c++) {
            unsigned u = ordf(vv[c]);
            if (u >= cut && u > LOU) {
                int gid = 4 * t + c;
                int pos = atomicAdd(&g_count, 1);
                if (pos < MAXC) {
                    g_candKey[pos] = ((unsigned long long)u << 32) | (unsigned)(~gid);
                    float imw = read_dim(pw);
                    float imh = read_dim(ph);
                    g_candBox[pos] = make_box(((const float4*)anc)[gid],
                                              ((const float4*)reg)[gid], imh, imw);
                }
            }
        }
    } else {
        int gid = (n4 << 2) + (t - n4);     // tail scalars (N % 4)
        if (gid < N) {
            unsigned u = ordf(g_scores[gid]);
            if (u >= cut && u > LOU) {
                int pos = atomicAdd(&g_count, 1);
                if (pos < MAXC) {
                    g_candKey[pos] = ((unsigned long long)u << 32) | (unsigned)(~gid);
                    float imw = read_dim(pw);
                    float imh = read_dim(ph);
                    g_candBox[pos] = make_box(((const float4*)anc)[gid],
                                              ((const float4*)reg)[gid], imh, imw);
                }
            }
        }
    }
}

// ---------------------------------------------------------------------------
// Kernel 3: single block. O(n^2) parallel rank, (row,word)-parallel div-free
// suppression bitmatrix, per-chunk sSup recompute, fast-path chunk resolve
// (exact greedy order), hoisted-load class argmax, output. Exact fallback.
// ---------------------------------------------------------------------------
__global__ void nms_kernel(float* __restrict__ out,
                           const float* __restrict__ cls,
                           const float* __restrict__ reg,
                           const float* __restrict__ anc,
                           const void* ph, const void* pw,
                           int N, int C) {
    __shared__ __align__(16) unsigned char sBuf[MAXC * 8 + MAXC * 8 + MAXC * 16 + MAXC * WORDS * 4];
    unsigned long long* sKeyRaw = (unsigned long long*)sBuf;
    unsigned long long* sKey    = (unsigned long long*)(sBuf + MAXC * 8);
    float4*   sCBox = (float4*)(sBuf + MAXC * 16);
    unsigned* sMat  = (unsigned*)(sBuf + MAXC * 32);
    unsigned long long* sTile = (unsigned long long*)sBuf;   // fallback alias

    __shared__ int    sOrder[MAXDET];
    __shared__ float4 sSelBox[MAXDET];
    __shared__ int    sSelIdx[MAXDET];
    __shared__ float  sSelScore[MAXDET];
    __shared__ int    sNsel, sSup1, sTotal;
    __shared__ unsigned sMaxu;
    __shared__ float4 sBx;
    __shared__ unsigned long long sWarp[16];
    __shared__ unsigned long long sTileP[3];

    int tid  = threadIdx.x;
    int wid  = tid >> 5;
    int lane = tid & 31;
    const unsigned FULL = 0xffffffffu;

    cudaGridDependencySynchronize();

    if (tid == 0) {
        sNsel  = 0;
        sTotal = g_count;
        sMaxu  = g_maxu;
        g_count = 0;          // reset for next graph replay
        g_maxu  = 0u;
    }
    __syncthreads();

    unsigned maxu = sMaxu;
    unsigned cutU = (maxu > LOU + 1u + SPAN) ? (maxu - SPAN) : (LOU + 1u);
    bool ovf = sTotal > MAXC;
    int  cnt = ovf ? 0 : sTotal;

    // ---- load keys + boxes ----
    unsigned long long myKey = 0ull;
    float4 myBox;
    if (tid < cnt) {
        myKey = g_candKey[tid];
        myBox = g_candBox[tid];
        sKeyRaw[tid] = myKey;
    }
    __syncthreads();

    // ---- O(n^2) parallel rank + scatter (descending) ----
    if (tid < cnt) {
        int rank = 0;
        for (int j = 0; j < cnt; j++)
            rank += (sKeyRaw[j] > myKey);
        sKey[rank]  = myKey;
        sCBox[rank] = myBox;
    }
    __syncthreads();

    // ---- suppression bitmatrix, parallel over (row, word) tasks ----
    int nW = (cnt + 31) >> 5;
    int tasks = cnt * nW;
    for (int t = tid; t < tasks; t += NMS_T) {
        int r = t / nW;
        int w = t - r * nW;
        float4 br = sCBox[r];
        unsigned mm = 0;
        int base = w << 5;
        int lim  = min(32, cnt - base);
        for (int b = 0; b < lim; b++)
            mm |= ((unsigned)iou_gt_half(br, sCBox[base + b])) << b;
        sMat[r * WORDS + w] = mm;
    }
    __syncthreads();

    // ---- greedy resolve in sorted order (warp 0) ----
    if (tid < 32) {
        int nsel = 0;
        for (int cb = 0; cb < cnt && nsel < MAXDET; cb += 32) {
            int cw = cb >> 5;
            unsigned supW = 0;
            for (int j = tid; j < nsel; j += 32)
                supW |= sMat[sOrder[j] * WORDS + cw];
            #pragma unroll
            for (int off = 16; off; off >>= 1)
                supW |= __shfl_xor_sync(FULL, supW, off);

            bool valid = (cb + tid) < cnt;
            bool alive = valid && !((supW >> tid) & 1u);
            unsigned myRow = valid ? sMat[(cb + tid) * WORDS + cw] : 0u;
            unsigned am = __ballot_sync(FULL, alive);
            unsigned conf = myRow & am & ((1u << tid) - 1u);
            bool hasConf = alive && (conf != 0u);

            unsigned selM;
            if (!__any_sync(FULL, hasConf)) {
                int room = MAXDET - nsel;
                if (__popc(am) <= room) {
                    selM = am;
                } else {
                    int myrank = __popc(am & ((1u << tid) - 1u));
                    selM = __ballot_sync(FULL, alive && (myrank < room));
                }
                if ((selM >> tid) & 1u)
                    sOrder[nsel + __popc(selM & ((1u << tid) - 1u))] = cb + tid;
                nsel += __popc(selM);
            } else {
                selM = 0;
                while (am && nsel < MAXDET) {
                    int l = __ffs(am) - 1;
                    selM |= 1u << l;
                    unsigned rl = sMat[(cb + l) * WORDS + cw];
                    if (tid == l) alive = false;
                    else if (tid > l && ((rl >> tid) & 1u)) alive = false;
                    nsel++;
                    am = __ballot_sync(FULL, alive);
                }
                int bse = nsel - __popc(selM);
                if ((selM >> tid) & 1u)
                    sOrder[bse + __popc(selM & ((1u << tid) - 1u))] = cb + tid;
            }
            __syncwarp();
        }
        if (tid == 0) sNsel = nsel;
    }
    __syncthreads();
    int nsel = sNsel;

    if (tid < nsel) {
        int o = sOrder[tid];
        unsigned long long key = sKey[o];
        sSelBox[tid]   = sCBox[o];
        sSelScore[tid] = unordf((unsigned)(key >> 32));
        sSelIdx[tid]   = (int)(~(unsigned)(key & 0xffffffffu));
    }
    __syncthreads();

    // ---- exact fallback (overflow / exhausted window only) ----
    if (nsel < MAXDET && (ovf || cutU > LOU + 1u)) {
        float imw = read_dim(pw);
        float imh = read_dim(ph);
        unsigned tauOrd = ovf ? 0xFFFFFFFFu : cutU;
        int T = (N + TILE - 1) / TILE;
        for (int t = tid; t < TMAX; t += NMS_T) {
            unsigned long long best = 0ull;
            if (t < T) {
                int bb = t * TILE;
                for (int k = 0; k < TILE; k++) {
                    int ii = bb + k;
                    if (ii >= N) break;
                    unsigned u = ordf(g_scores[ii]);
                    if (u >= tauOrd) continue;     // consumed in phase 1
                    unsigned long long kk =
                        ((unsigned long long)u << 32) | (unsigned)(~ii);
                    if (kk > best) best = kk;
                }
            }
            sTile[t] = best;
        }
        __syncthreads();

        while (nsel < MAXDET) {
            unsigned long long best = 0ull;
            #pragma unroll
            for (int k = 0; k < TMAX / NMS_T; k++) {
                unsigned long long v = sTile[tid + k * NMS_T];
                best = (v > best) ? v : best;
            }
            #pragma unroll
            for (int off = 16; off; off >>= 1) {
                unsigned long long o = __shfl_down_sync(FULL, best, off);
                best = (o > best) ? o : best;
            }
            if (lane == 0) sWarp[wid] = best;
            __syncthreads();
            if (tid < 32) {
                unsigned long long v = (tid < 16) ? sWarp[tid] : 0ull;
                #pragma unroll
                for (int off = 8; off; off >>= 1) {
                    unsigned long long o = __shfl_down_sync(FULL, v, off);
                    v = (o > v) ? o : v;
                }
                if (tid == 0) sWarp[0] = v;
            }
            __syncthreads();
            unsigned long long win = sWarp[0];
            unsigned hi = (unsigned)(win >> 32);
            if (hi <= 0x007FFFFFu) break;
            int   i   = (int)(~(unsigned)(win & 0xffffffffu));
            float val = unordf(hi);
            if (tid == 0) {
                g_scores[i] = -INFINITY;
                sBx = make_box(((const float4*)anc)[i],
                               ((const float4*)reg)[i], imh, imw);
                sSup1 = 0;
            }
            __syncthreads();
            int t = i / TILE;
            if (tid < TILE) {
                int ii = t * TILE + tid;
                unsigned u = (ii < N) ? ordf(g_scores[ii]) : 0x007FFFFFu;
                unsigned long long kk = 0ull;
                if (u < tauOrd)
                    kk = ((unsigned long long)u << 32) | (unsigned)(~ii);
                #pragma unroll
                for (int off = 16; off; off >>= 1) {
                    unsigned long long o = __shfl_down_sync(FULL, kk, off);
                    kk = (o > kk) ? o : kk;
                }
                if (lane == 0) sTileP[wid] = kk;
            }
            if (tid >= 128 && tid < 128 + nsel) {
                if (iou_gt_half(sSelBox[tid - 128], sBx)) sSup1 = 1;
            }
            __syncthreads();
            if (tid == 0) {
                unsigned long long kk = sTileP[0];
                if (sTileP[1] > kk) kk = sTileP[1];
                if (sTileP[2] > kk) kk = sTileP[2];
                sTile[t] = kk;
                if (!sSup1) {
                    sSelBox[nsel] = sBx; sSelIdx[nsel] = i; sSelScore[nsel] = val;
                    sNsel = nsel + 1;
                }
            }
            __syncthreads();
            nsel = sNsel;
        }
    }
    __syncthreads();
    nsel = sNsel;

    // ---- class argmax for selected rows (warp per row, hoisted loads) ----
    if (C <= 96) {
        float b0[7], b1[7], b2[7];
        int nR = 0;
        for (int r = wid; r < nsel; r += 16) {
            const float* row = cls + (long long)sSelIdx[r] * C;
            b0[nR] = (lane      < C) ? row[lane]      : -INFINITY;
            b1[nR] = (lane + 32 < C) ? row[lane + 32] : -INFINITY;
            b2[nR] = (lane + 64 < C) ? row[lane + 64] : -INFINITY;
            nR++;
        }
        int k = 0;
        for (int r = wid; r < nsel; r += 16, k++) {
            float best = b0[k];
            int   bidx = lane;
            if (b1[k] > best) { best = b1[k]; bidx = lane + 32; }
            if (b2[k] > best) { best = b2[k]; bidx = lane + 64; }
            #pragma unroll
            for (int off = 16; off; off >>= 1) {
                float ov = __shfl_down_sync(FULL, best, off);
                int   oi = __shfl_down_sync(FULL, bidx, off);
                if (ov > best || (ov == best && oi < bidx)) { best = ov; bidx = oi; }
            }
            if (lane == 0) out[100 + r] = (float)bidx;
        }
    } else {
        for (int r = wid; r < nsel; r += 16) {
            int i = sSelIdx[r];
            const float* row = cls + (long long)i * C;
            float best = -INFINITY;
            int   bidx = 0x7fffffff;
            for (int j = lane; j < C; j += 32) {
                float v = row[j];
                if (v > best) { best = v; bidx = j; }
            }
            #pragma unroll
            for (int off = 16; off; off >>= 1) {
                float ov = __shfl_down_sync(FULL, best, off);
                int   oi = __shfl_down_sync(FULL, bidx, off);
                if (ov > best || (ov == best && oi < bidx)) { best = ov; bidx = oi; }
            }
            if (lane == 0) out[100 + r] = (float)bidx;
        }
    }

    for (int r = tid; r < MAXDET; r += NMS_T) {
        bool k = r < nsel;
        out[r]       = k ? sSelScore[r] : 0.0f;
        out[600 + r] = k ? 1.0f : 0.0f;
        float4 b = k ? sSelBox[r] : make_float4(0.f, 0.f, 0.f, 0.f);
        out[200 + 4 * r + 0] = b.x;
        out[200 + 4 * r + 1] = b.y;
        out[200 + 4 * r + 2] = b.z;
        out[200 + 4 * r + 3] = b.w;
        if (!k) out[100 + r] = -1.0f;
    }
}

extern "C" void kernel_launch(void* const* d_in, const int* in_sizes, int n_in,
                              void* d_out, int out_size) {
    const float* cls = (const float*)d_in[0];
    const float* reg = (const float*)d_in[1];
    const float* anc = (const float*)d_in[2];
    const void*  ph  = d_in[3];
    const void*  pw  = d_in[4];

    int N = in_sizes[2] / 4;
    int C = in_sizes[0] / N;

    if (C == 90) {
        int pairs   = N >> 1;
        int nTiles  = (pairs + DT_PAIRS - 1) / DT_PAIRS;
        int blocksD = (nTiles + DT_TPB - 1) / DT_TPB;
        if (blocksD < 1) blocksD = 1;
        decode90_kernel<<<blocksD, 256>>>(cls, N);
    } else {
        int blocksD = (N + 7) / 8;
        decodegen_kernel<<<blocksD, 256>>>(cls, N, C);
    }

    // PDL: pre-launch overlap; device-side cudaGridDependencySynchronize()
    // provides ordering.
    cudaLaunchAttribute pdlAttr[1];
    pdlAttr[0].id = cudaLaunchAttributeProgrammaticStreamSerialization;
    pdlAttr[0].val.programmaticStreamSerializationAllowed = 1;

    {
        int n4 = N >> 2;
        int tail = N - (n4 << 2);
        int threadsC = n4 + tail;
        cudaLaunchConfig_t cfg = {};
        cfg.gridDim  = dim3((threadsC + 255) / 256);
        cfg.blockDim = dim3(256);
        cfg.attrs    = pdlAttr;
        cfg.numAttrs = 1;
        cudaLaunchKernelEx(&cfg, compact_kernel, reg, anc, ph, pw, N);
    }
    {
        cudaLaunchConfig_t cfg = {};
        cfg.gridDim  = dim3(1);
        cfg.blockDim = dim3(NMS_T);
        cfg.attrs    = pdlAttr;
        cfg.numAttrs = 1;
        cudaLaunchKernelEx(&cfg, nms_kernel, (float*)d_out, cls, reg, anc,
                           ph, pw, N, C);
    }
}

// round 16
// speedup vs baseline: 1.0457x; 1.0457x over previous
#include <cuda_runtime.h>
#include <math.h>

#define N_MAX   196608
#define TILE    96
#define TMAX    2048
#define MAXDET  100
#define MAXC    448           // candidate cap (matrix capacity)
#define WORDS   14            // MAXC / 32
#define SPAN    128u          // window below max, ordered-ulp units
#define LOU     0xBC23D70Au   // ordf(0.01f)
#define NMS_T   512

// decode tiling (C==90 fast path) — R14 measured-optimal config
#define DT_PAIRS 32                     // pairs per tile
#define DT_BYTES (DT_PAIRS * 720)       // 23040 B (45 float4 per pair)
#define DT_TPB   4                      // tiles per block, depth-2 ping-pong

__device__ float              g_scores[N_MAX];
__device__ unsigned           g_maxu;     // zero-init; reset by nms each replay
__device__ int                g_count;    // reset by nms each replay
__device__ unsigned long long g_candKey[MAXC];
__device__ float4             g_candBox[MAXC];

__device__ __forceinline__ unsigned ordf(float f) {
    unsigned u = __float_as_uint(f);
    return (u & 0x80000000u) ? ~u : (u | 0x80000000u);
}
__device__ __forceinline__ float unordf(unsigned u) {
    return __uint_as_float((u & 0x80000000u) ? (u ^ 0x80000000u) : ~u);
}
__device__ __forceinline__ float read_dim(const void* p) {
    int iv = *(const int*)p;
    if (iv >= 1 && iv <= (1 << 20)) return (float)iv;
    float fv = *(const float*)p;
    if (fv >= 1.0f && fv <= 1048576.0f) return fv;
    double dv = *(const double*)p;
    if (dv >= 1.0 && dv <= 1048576.0) return (float)dv;
    long long lv = *(const long long*)p;
    return (float)lv;
}
// iou > 0.5  <=>  inter > 0.5*den  (den > 0 always; exact comparison, no div)
__device__ __forceinline__ bool iou_gt_half(float4 A, float4 B) {
    float x1 = fmaxf(A.x, B.x), y1 = fmaxf(A.y, B.y);
    float x2 = fminf(A.z, B.z), y2 = fminf(A.w, B.w);
    float inter = fmaxf(x2 - x1, 0.0f) * fmaxf(y2 - y1, 0.0f);
    float a1 = (A.z - A.x) * (A.w - A.y);
    float a2 = (B.z - B.x) * (B.w - B.y);
    float den = ((a1 + a2) - inter) + 1e-8f;   // match reference association
    return inter > 0.5f * den;
}
__device__ __forceinline__ float4 make_box(float4 a, float4 r,
                                           float imh, float imw) {
    float wa  = a.z - a.x;
    float ha  = a.w - a.y;
    float cxa = a.x + 0.5f * wa;
    float cya = a.y + 0.5f * ha;
    float cx  = cxa + r.x * 0.1f * wa;
    float cy  = cya + r.y * 0.1f * ha;
    float w   = expf(r.z * 0.2f) * wa;
    float h   = expf(r.w * 0.2f) * ha;
    float4 b;
    b.x = fminf(fmaxf(cx - 0.5f * w, 0.0f), imw);
    b.y = fminf(fmaxf(cy - 0.5f * h, 0.0f), imh);
    b.z = fminf(fmaxf(cx + 0.5f * w, 0.0f), imw);
    b.w = fminf(fmaxf(cy + 0.5f * h, 0.0f), imh);
    return b;
}
__device__ __forceinline__ unsigned ord4max(float4 v) {
    return ordf(fmaxf(fmaxf(v.x, v.y), fmaxf(v.z, v.w)));
}
__device__ __forceinline__ unsigned smem_u32(const void* p) {
    return (unsigned)__cvta_generic_to_shared(p);
}
__device__ __forceinline__ void mbar_init(unsigned mb, unsigned cnt) {
    asm volatile("mbarrier.init.shared.b64 [%0], %1;" :: "r"(mb), "r"(cnt) : "memory");
}
__device__ __forceinline__ void mbar_expect_tx(unsigned mb, unsigned bytes) {
    asm volatile("mbarrier.arrive.expect_tx.shared.b64 _, [%0], %1;"
                 :: "r"(mb), "r"(bytes) : "memory");
}
__device__ __forceinline__ void mbar_wait(unsigned mb, unsigned parity) {
    asm volatile(
        "{\n\t.reg .pred P;\n\t"
        "WAIT_%=:\n\t"
        "mbarrier.try_wait.parity.acquire.cta.shared::cta.b64 P, [%0], %1;\n\t"
        "@!P bra WAIT_%=;\n\t}"
        :: "r"(mb), "r"(parity) : "memory");
}
__device__ __forceinline__ void bulk_ld(unsigned sdst, const void* gsrc,
                                        unsigned bytes, unsigned mb) {
    asm volatile(
        "cp.async.bulk.shared::cta.global.mbarrier::complete_tx::bytes "
        "[%0], [%1], %2, [%3];"
        :: "r"(sdst), "l"(gsrc), "r"(bytes), "r"(mb) : "memory");
}

// ---------------------------------------------------------------------------
// Kernel 1 (C==90): R14 bulk-async double-buffered decode + FUSED candidate
// collection. Appends candidates with u + SPAN >= runningMax (running <=
// final max => superset of the final window; nms filters by final cut).
// Per-pair scores parked in 1KB smem to keep hot-loop reg pressure at R14
// levels. Overflow of MAXC routes to nms's exact fallback.
// ---------------------------------------------------------------------------
__global__ void __launch_bounds__(256)
decode90_kernel(const float* __restrict__ cls,
                const float* __restrict__ reg,
                const float* __restrict__ anc,
                const void* ph, const void* pw, int N) {
    __shared__ __align__(128) char sBuf[2][DT_BYTES];
    __shared__ __align__(8) unsigned long long sMbar[2];
    __shared__ unsigned sU[DT_TPB][DT_PAIRS][2];   // per-pair ordered scores
    __shared__ unsigned sRun;
    const unsigned FULL = 0xffffffffu;
    int tid = threadIdx.x;
    int sub = tid & 7;
    int grp = tid >> 3;                  // pair-within-tile [0,32)
    int pairs = N >> 1;
    int nTiles = (pairs + DT_PAIRS - 1) / DT_PAIRS;
    long long tile0 = (long long)blockIdx.x * DT_TPB;
    int nT = (int)min((long long)DT_TPB, (long long)nTiles - tile0);

    unsigned mb0 = smem_u32(&sMbar[0]);
    unsigned mb1 = smem_u32(&sMbar[1]);
    unsigned sb0 = smem_u32(&sBuf[0][0]);
    unsigned sb1 = smem_u32(&sBuf[1][0]);

    // zero the score stash (256 slots = 1 per thread)
    ((unsigned*)sU)[tid] = 0u;

    if (nT > 0) {
        if (tid == 0) {
            mbar_init(mb0, 1);
            mbar_init(mb1, 1);
        }
        __syncthreads();

        // prime: first up-to-2 tile loads
        if (tid == 0) {
            int prime = nT < 2 ? nT : 2;
            for (int k = 0; k < prime; k++) {
                long long t = tile0 + k;
                int pIn = (int)min((long long)DT_PAIRS, (long long)pairs - t * DT_PAIRS);
                unsigned bytes = (unsigned)(pIn * 720);
                unsigned mb = k ? mb1 : mb0;
                unsigned sb = k ? sb1 : sb0;
                mbar_expect_tx(mb, bytes);
                bulk_ld(sb, (const char*)cls + t * (long long)DT_BYTES, bytes, mb);
            }
        }

        unsigned wm = 0u;
        for (int k = 0; k < nT; k++) {
            int b = k & 1;
            unsigned mb = b ? mb1 : mb0;
            mbar_wait(mb, (unsigned)((k >> 1) & 1));

            long long t = tile0 + k;
            int pIn = (int)min((long long)DT_PAIRS, (long long)pairs - t * DT_PAIRS);

            unsigned mA = 0u, mB = 0u;
            if (grp < pIn) {
                const float4* rowp = (const float4*)&sBuf[b][0] + grp * 45;
                float4 va[6];
                #pragma unroll
                for (int it = 0; it < 6; it++) {
                    int q  = sub + it * 8;
                    int qc = (q < 45) ? q : 0;
                    va[it] = rowp[qc];
                }
                #pragma unroll
                for (int it = 0; it < 6; it++) {
                    int q = sub + it * 8;
                    if (q < 45) {
                        float4 x = va[it];
                        if (q < 22) {
                            mA = max(mA, ord4max(x));
                        } else if (q == 22) {   // floats 88..91: x,y->A; z,w->B
                            mA = max(mA, ordf(fmaxf(x.x, x.y)));
                            mB = max(mB, ordf(fmaxf(x.z, x.w)));
                        } else {
                            mB = max(mB, ord4max(x));
                        }
                    }
                }
            }
            #pragma unroll
            for (int off = 1; off <= 4; off <<= 1) {
                mA = max(mA, __shfl_xor_sync(FULL, mA, off));
                mB = max(mB, __shfl_xor_sync(FULL, mB, off));
            }
            if (grp < pIn && sub < 2) {
                unsigned u = sub ? mB : mA;
                float best = unordf(u);
                g_scores[2 * (t * DT_PAIRS + grp) + sub] =
                    (best > 0.01f) ? best : -INFINITY;
                sU[k][grp][sub] = u;
            }
            wm = max(wm, max(mA, mB));

            __syncthreads();   // all reads of buffer b done before refill
            if (tid == 0 && k + 2 < nT) {
                long long t2 = tile0 + k + 2;
                int pIn2 = (int)min((long long)DT_PAIRS, (long long)pairs - t2 * DT_PAIRS);
                unsigned bytes = (unsigned)(pIn2 * 720);
                mbar_expect_tx(mb, bytes);
                bulk_ld(b ? sb1 : sb0,
                        (const char*)cls + t2 * (long long)DT_BYTES, bytes, mb);
            }
        }

        // one global atomic per warp
        wm = max(wm, __shfl_xor_sync(FULL, wm, 8));
        wm = max(wm, __shfl_xor_sync(FULL, wm, 16));
        #pragma unroll
        for (int off = 1; off <= 4; off <<= 1)
            wm = max(wm, __shfl_xor_sync(FULL, wm, off));
        if ((tid & 31) == 0) atomicMax(&g_maxu, wm);

        // running max (includes this block's contributions), block-wide
        __syncthreads();
        if (tid == 0) sRun = atomicMax(&g_maxu, 0u);
        __syncthreads();
        unsigned running = sRun;

        // candidate append: superset of final window (running <= final max)
        if (tid < 64) {
            int g = tid >> 1, s = tid & 1;
            float imw = read_dim(pw);
            float imh = read_dim(ph);
            #pragma unroll
            for (int k = 0; k < DT_TPB; k++) {
                unsigned u = sU[k][g][s];
                if (u > LOU && u + SPAN >= running) {
                    long long t = tile0 + k;
                    int idx = (int)(2 * (t * DT_PAIRS + g) + s);
                    int pos = atomicAdd(&g_count, 1);
                    if (pos < MAXC) {
                        g_candKey[pos] = ((unsigned long long)u << 32)
                                       | (unsigned)(~idx);
                        g_candBox[pos] = make_box(((const float4*)anc)[idx],
                                                  ((const float4*)reg)[idx],
                                                  imh, imw);
                    }
                }
            }
        }
    }

    // odd-N tail anchor
    if ((N & 1) && blockIdx.x == 0 && tid == 0) {
        const float* row = cls + (long long)(N - 1) * 90;
        unsigned u = 0u;
        for (int j = 0; j < 90; j++) u = max(u, ordf(row[j]));
        float best = unordf(u);
        g_scores[N - 1] = (best > 0.01f) ? best : -INFINITY;
        unsigned old = atomicMax(&g_maxu, u);
        unsigned running = max(old, u);
        if (u > LOU && u + SPAN >= running) {
            int idx = N - 1;
            int pos = atomicAdd(&g_count, 1);
            if (pos < MAXC) {
                g_candKey[pos] = ((unsigned long long)u << 32) | (unsigned)(~idx);
                g_candBox[pos] = make_box(((const float4*)anc)[idx],
                                          ((const float4*)reg)[idx],
                                          read_dim(ph), read_dim(pw));
            }
        }
    }
}

// Generic-C path: warp per anchor, fused candidate append.
__global__ void decodegen_kernel(const float* __restrict__ cls,
                                 const float* __restrict__ reg,
                                 const float* __restrict__ anc,
                                 const void* ph, const void* pw,
                                 int N, int C) {
    const unsigned FULL = 0xffffffffu;
    int warp = (blockIdx.x * blockDim.x + threadIdx.x) >> 5;
    int lane = threadIdx.x & 31;
    if (warp >= N) return;
    const float* row = cls + (long long)warp * C;
    unsigned u = 0u;
    for (int j = lane; j < C; j += 32) u = max(u, ordf(row[j]));
    #pragma unroll
    for (int off = 16; off; off >>= 1)
        u = max(u, __shfl_xor_sync(FULL, u, off));
    if (lane == 0) {
        float best = unordf(u);
        g_scores[warp] = (best > 0.01f) ? best : -INFINITY;
        unsigned old = atomicMax(&g_maxu, u);
        unsigned running = max(old, u);
        if (u > LOU && u + SPAN >= running) {
            int pos = atomicAdd(&g_count, 1);
            if (pos < MAXC) {
                g_candKey[pos] = ((unsigned long long)u << 32) | (unsigned)(~warp);
                g_candBox[pos] = make_box(((const float4*)anc)[warp],
                                          ((const float4*)reg)[warp],
                                          read_dim(ph), read_dim(pw));
            }
        }
    }
}

// ---------------------------------------------------------------------------
// Kernel 2: single block. Filtered candidate load (final-cut), O(n^2) rank,
// (row,word)-parallel div-free bitmatrix, fast-path chunk resolve (exact
// greedy order), hoisted-load class argmax, output. Exact fallback.
// ---------------------------------------------------------------------------
__global__ void nms_kernel(float* __restrict__ out,
                           const float* __restrict__ cls,
                           const float* __restrict__ reg,
                           const float* __restrict__ anc,
                           const void* ph, const void* pw,
                           int N, int C) {
    __shared__ __align__(16) unsigned char sBuf[MAXC * 8 + MAXC * 8 + MAXC * 16 + MAXC * WORDS * 4];
    unsigned long long* sKeyRaw = (unsigned long long*)sBuf;
    unsigned long long* sKey    = (unsigned long long*)(sBuf + MAXC * 8);
    float4*   sCBox = (float4*)(sBuf + MAXC * 16);
    unsigned* sMat  = (unsigned*)(sBuf + MAXC * 32);
    float4*   sStage = (float4*)(sBuf + MAXC * 32);          // staging (pre-matrix)
    unsigned long long* sTile = (unsigned long long*)sBuf;   // fallback alias

    __shared__ int    sOrder[MAXDET];
    __shared__ float4 sSelBox[MAXDET];
    __shared__ int    sSelIdx[MAXDET];
    __shared__ float  sSelScore[MAXDET];
    __shared__ int    sNsel, sSup1, sTotal, sCnt;
    __shared__ unsigned sMaxu;
    __shared__ float4 sBx;
    __shared__ unsigned long long sWarp[16];
    __shared__ unsigned long long sTileP[3];

    int tid  = threadIdx.x;
    int wid  = tid >> 5;
    int lane = tid & 31;
    const unsigned FULL = 0xffffffffu;

    cudaGridDependencySynchronize();

    if (tid == 0) {
        sNsel  = 0;
        sCnt   = 0;
        sTotal = g_count;
        sMaxu  = g_maxu;
        g_count = 0;          // reset for next graph replay
        g_maxu  = 0u;
    }
    __syncthreads();

    unsigned maxu = sMaxu;
    unsigned cutU = (maxu > LOU + 1u + SPAN) ? (maxu - SPAN) : (LOU + 1u);
    bool ovf = sTotal > MAXC;

    // ---- filtered load: keep only u >= final cut (exact window set) ----
    if (!ovf && tid < sTotal) {
        unsigned long long key = g_candKey[tid];
        if ((unsigned)(key >> 32) >= cutU) {
            int pos = atomicAdd(&sCnt, 1);
            sKeyRaw[pos] = key;
            sStage[pos]  = g_candBox[tid];
        }
    }
    __syncthreads();
    int cnt = ovf ? 0 : sCnt;

    // ---- O(n^2) parallel rank + scatter (descending) ----
    if (tid < cnt) {
        unsigned long long myKey = sKeyRaw[tid];
        float4 myBox = sStage[tid];
        int rank = 0;
        for (int j = 0; j < cnt; j++)
            rank += (sKeyRaw[j] > myKey);
        sKey[rank]  = myKey;
        sCBox[rank] = myBox;
    }
    __syncthreads();

    // ---- suppression bitmatrix, parallel over (row, word) tasks ----
    int nW = (cnt + 31) >> 5;
    int tasks = cnt * nW;
    for (int t = tid; t < tasks; t += NMS_T) {
        int r = t / nW;
        int w = t - r * nW;
        float4 br = sCBox[r];
        unsigned mm = 0;
        int base = w << 5;
        int lim  = min(32, cnt - base);
        for (int b = 0; b < lim; b++)
            mm |= ((unsigned)iou_gt_half(br, sCBox[base + b])) << b;
        sMat[r * WORDS + w] = mm;
    }
    __syncthreads();

    // ---- greedy resolve in sorted order (warp 0) ----
    if (tid < 32) {
        int nsel = 0;
        for (int cb = 0; cb < cnt && nsel < MAXDET; cb += 32) {
            int cw = cb >> 5;
            unsigned supW = 0;
            for (int j = tid; j < nsel; j += 32)
                supW |= sMat[sOrder[j] * WORDS + cw];
            #pragma unroll
            for (int off = 16; off; off >>= 1)
                supW |= __shfl_xor_sync(FULL, supW, off);

            bool valid = (cb + tid) < cnt;
            bool alive = valid && !((supW >> tid) & 1u);
            unsigned myRow = valid ? sMat[(cb + tid) * WORDS + cw] : 0u;
            unsigned am = __ballot_sync(FULL, alive);
            unsigned conf = myRow & am & ((1u << tid) - 1u);
            bool hasConf = alive && (conf != 0u);

            unsigned selM;
            if (!__any_sync(FULL, hasConf)) {
                int room = MAXDET - nsel;
                if (__popc(am) <= room) {
                    selM = am;
                } else {
                    int myrank = __popc(am & ((1u << tid) - 1u));
                    selM = __ballot_sync(FULL, alive && (myrank < room));
                }
                if ((selM >> tid) & 1u)
                    sOrder[nsel + __popc(selM & ((1u << tid) - 1u))] = cb + tid;
                nsel += __popc(selM);
            } else {
                selM = 0;
                while (am && nsel < MAXDET) {
                    int l = __ffs(am) - 1;
                    selM |= 1u << l;
                    unsigned rl = sMat[(cb + l) * WORDS + cw];
                    if (tid == l) alive = false;
                    else if (tid > l && ((rl >> tid) & 1u)) alive = false;
                    nsel++;
                    am = __ballot_sync(FULL, alive);
                }
                int bse = nsel - __popc(selM);
                if ((selM >> tid) & 1u)
                    sOrder[bse + __popc(selM & ((1u << tid) - 1u))] = cb + tid;
            }
            __syncwarp();
        }
        if (tid == 0) sNsel = nsel;
    }
    __syncthreads();
    int nsel = sNsel;

    if (tid < nsel) {
        int o = sOrder[tid];
        unsigned long long key = sKey[o];
        sSelBox[tid]   = sCBox[o];
        sSelScore[tid] = unordf((unsigned)(key >> 32));
        sSelIdx[tid]   = (int)(~(unsigned)(key & 0xffffffffu));
    }
    __syncthreads();

    // ---- exact fallback (overflow / exhausted window only) ----
    if (nsel < MAXDET && (ovf || cutU > LOU + 1u)) {
        float imw = read_dim(pw);
        float imh = read_dim(ph);
        unsigned tauOrd = ovf ? 0xFFFFFFFFu : cutU;
        int T = (N + TILE - 1) / TILE;
        for (int t = tid; t < TMAX; t += NMS_T) {
            unsigned long long best = 0ull;
            if (t < T) {
                int bb = t * TILE;
                for (int k = 0; k < TILE; k++) {
                    int ii = bb + k;
                    if (ii >= N) break;
                    unsigned u = ordf(g_scores[ii]);
                    if (u >= tauOrd) continue;     // consumed in phase 1
                    unsigned long long kk =
                        ((unsigned long long)u << 32) | (unsigned)(~ii);
                    if (kk > best) best = kk;
                }
            }
            sTile[t] = best;
        }
        __syncthreads();

        while (nsel < MAXDET) {
            unsigned long long best = 0ull;
            #pragma unroll
            for (int k = 0; k < TMAX / NMS_T; k++) {
                unsigned long long v = sTile[tid + k * NMS_T];
                best = (v > best) ? v : best;
            }
            #pragma unroll
            for (int off = 16; off; off >>= 1) {
                unsigned long long o = __shfl_down_sync(FULL, best, off);
                best = (o > best) ? o : best;
            }
            if (lane == 0) sWarp[wid] = best;
            __syncthreads();
            if (tid < 32) {
                unsigned long long v = (tid < 16) ? sWarp[tid] : 0ull;
                #pragma unroll
                for (int off = 8; off; off >>= 1) {
                    unsigned long long o = __shfl_down_sync(FULL, v, off);
                    v = (o > v) ? o : v;
                }
                if (tid == 0) sWarp[0] = v;
            }
            __syncthreads();
            unsigned long long win = sWarp[0];
            unsigned hi = (unsigned)(win >> 32);
            if (hi <= 0x007FFFFFu) break;
            int   i   = (int)(~(unsigned)(win & 0xffffffffu));
            float val = unordf(hi);
            if (tid == 0) {
                g_scores[i] = -INFINITY;
                sBx = make_box(((const float4*)anc)[i],
                               ((const float4*)reg)[i], imh, imw);
                sSup1 = 0;
            }
            __syncthreads();
            int t = i / TILE;
            if (tid < TILE) {
                int ii = t * TILE + tid;
                unsigned u = (ii < N) ? ordf(g_scores[ii]) : 0x007FFFFFu;
                unsigned long long kk = 0ull;
                if (u < tauOrd)
                    kk = ((unsigned long long)u << 32) | (unsigned)(~ii);
                #pragma unroll
                for (int off = 16; off; off >>= 1) {
                    unsigned long long o = __shfl_down_sync(FULL, kk, off);
                    kk = (o > kk) ? o : kk;
                }
                if (lane == 0) sTileP[wid] = kk;
            }
            if (tid >= 128 && tid < 128 + nsel) {
                if (iou_gt_half(sSelBox[tid - 128], sBx)) sSup1 = 1;
            }
            __syncthreads();
            if (tid == 0) {
                unsigned long long kk = sTileP[0];
                if (sTileP[1] > kk) kk = sTileP[1];
                if (sTileP[2] > kk) kk = sTileP[2];
                sTile[t] = kk;
                if (!sSup1) {
                    sSelBox[nsel] = sBx; sSelIdx[nsel] = i; sSelScore[nsel] = val;
                    sNsel = nsel + 1;
                }
            }
            __syncthreads();
            nsel = sNsel;
        }
    }
    __syncthreads();
    nsel = sNsel;

    // ---- class argmax for selected rows (warp per row, hoisted loads) ----
    if (C <= 96) {
        float b0[7], b1[7], b2[7];
        int nR = 0;
        for (int r = wid; r < nsel; r += 16) {
            const float* row = cls + (long long)sSelIdx[r] * C;
            b0[nR] = (lane      < C) ? row[lane]      : -INFINITY;
            b1[nR] = (lane + 32 < C) ? row[lane + 32] : -INFINITY;
            b2[nR] = (lane + 64 < C) ? row[lane + 64] : -INFINITY;
            nR++;
        }
        int k = 0;
        for (int r = wid; r < nsel; r += 16, k++) {
            float best = b0[k];
            int   bidx = lane;
            if (b1[k] > best) { best = b1[k]; bidx = lane + 32; }
            if (b2[k] > best) { best = b2[k]; bidx = lane + 64; }
            #pragma unroll
            for (int off = 16; off; off >>= 1) {
                float ov = __shfl_down_sync(FULL, best, off);
                int   oi = __shfl_down_sync(FULL, bidx, off);
                if (ov > best || (ov == best && oi < bidx)) { best = ov; bidx = oi; }
            }
            if (lane == 0) out[100 + r] = (float)bidx;
        }
    } else {
        for (int r = wid; r < nsel; r += 16) {
            int i = sSelIdx[r];
            const float* row = cls + (long long)i * C;
            float best = -INFINITY;
            int   bidx = 0x7fffffff;
            for (int j = lane; j < C; j += 32) {
                float v = row[j];
                if (v > best) { best = v; bidx = j; }
            }
            #pragma unroll
            for (int off = 16; off; off >>= 1) {
                float ov = __shfl_down_sync(FULL, best, off);
                int   oi = __shfl_down_sync(FULL, bidx, off);
                if (ov > best || (ov == best && oi < bidx)) { best = ov; bidx = oi; }
            }
            if (lane == 0) out[100 + r] = (float)bidx;
        }
    }

    for (int r = tid; r < MAXDET; r += NMS_T) {
        bool k = r < nsel;
        out[r]       = k ? sSelScore[r] : 0.0f;
        out[600 + r] = k ? 1.0f : 0.0f;
        float4 b = k ? sSelBox[r] : make_float4(0.f, 0.f, 0.f, 0.f);
        out[200 + 4 * r + 0] = b.x;
        out[200 + 4 * r + 1] = b.y;
        out[200 + 4 * r + 2] = b.z;
        out[200 + 4 * r + 3] = b.w;
        if (!k) out[100 + r] = -1.0f;
    }
}

extern "C" void kernel_launch(void* const* d_in, const int* in_sizes, int n_in,
                              void* d_out, int out_size) {
    const float* cls = (const float*)d_in[0];
    const float* reg = (const float*)d_in[1];
    const float* anc = (const float*)d_in[2];
    const void*  ph  = d_in[3];
    const void*  pw  = d_in[4];

    int N = in_sizes[2] / 4;
    int C = in_sizes[0] / N;

    if (C == 90) {
        int pairs   = N >> 1;
        int nTiles  = (pairs + DT_PAIRS - 1) / DT_PAIRS;
        int blocksD = (nTiles + DT_TPB - 1) / DT_TPB;
        if (blocksD < 1) blocksD = 1;
        decode90_kernel<<<blocksD, 256>>>(cls, reg, anc, ph, pw, N);
    } else {
        int blocksD = (N + 7) / 8;
        decodegen_kernel<<<blocksD, 256>>>(cls, reg, anc, ph, pw, N, C);
    }

    // PDL: pre-launch overlap; device-side cudaGridDependencySynchronize()
    // provides ordering.
    cudaLaunchAttribute pdlAttr[1];
    pdlAttr[0].id = cudaLaunchAttributeProgrammaticStreamSerialization;
    pdlAttr[0].val.programmaticStreamSerializationAllowed = 1;

    {
        cudaLaunchConfig_t cfg = {};
        cfg.gridDim  = dim3(1);
        cfg.blockDim = dim3(NMS_T);
        cfg.attrs    = pdlAttr;
        cfg.numAttrs = 1;
        cudaLaunchKernelEx(&cfg, nms_kernel, (float*)d_out, cls, reg, anc,
                           ph, pw, N, C);
    }
}